// round 4
// baseline (speedup 1.0000x reference)
#include <cuda_runtime.h>
#include <cuda_bf16.h>

// StandardDeviationPooling: 4x4 window, stride 2, VALID.
// Input:  [64, 1024, 1024, 1] fp32   Output: [64, 511*511] fp32
// std = sqrt(max(E[x^2] - E[x]^2, 0)) per window.
//
// R4: 4 output cols per thread from 3 float4/row (0.75 LDG.128 per output,
//     1.5x L1 amplification vs 2.0x before). 8 output rows per thread with
//     rolling 2-row pair sums (each input row loaded once per strip).

#define H_IN 1024
#define W_IN 1024
#define H_OUT 511
#define W_OUT 511
#define ROWS_PER_THREAD 8

__global__ __launch_bounds__(256)
void std_pool_kernel(const float* __restrict__ in, float* __restrict__ out) {
    const int c     = threadIdx.x;                      // col-quad index 0..127
    const int strip = blockIdx.y * 2 + threadIdx.y;     // 0..63
    const int r0    = strip * ROWS_PER_THREAD;          // first output row of strip
    const int b     = blockIdx.z;

    const float* __restrict__ inb  = in  + (size_t)b * H_IN * W_IN;
    float* __restrict__       outb = out + (size_t)b * H_OUT * W_OUT;

    const int  ic   = 8 * c;                 // first input col (thread covers 8c..8c+11)
    const bool has3 = (ic + 11) < W_IN;      // third float4 in-bounds (c < 127)
    const int  oc0  = 4 * c;

    const float inv_n = 1.0f / 16.0f;

    // previous pair-of-rows sums (s) and sums-of-squares (q) for 4 output cols
    float ps0 = 0.f, ps1 = 0.f, ps2 = 0.f, ps3 = 0.f;
    float pq0 = 0.f, pq1 = 0.f, pq2 = 0.f, pq3 = 0.f;

    #pragma unroll
    for (int j = 0; j <= ROWS_PER_THREAD; ++j) {
        const int irow = 2 * (r0 + j);
        float cs0 = 0.f, cs1 = 0.f, cs2 = 0.f, cs3 = 0.f;
        float cq0 = 0.f, cq1 = 0.f, cq2 = 0.f, cq3 = 0.f;

        if (irow + 1 < H_IN) {
            #pragma unroll
            for (int rr = 0; rr < 2; ++rr) {
                const float* rowp = inb + (size_t)(irow + rr) * W_IN + ic;
                const float4 a  = *reinterpret_cast<const float4*>(rowp);
                const float4 bb = *reinterpret_cast<const float4*>(rowp + 4);
                float4 cc;
                if (has3) cc = *reinterpret_cast<const float4*>(rowp + 8);
                else      cc = make_float4(0.f, 0.f, 0.f, 0.f);

                // pairwise partial sums shared across overlapping windows
                const float t01 = a.x + a.y,   t23 = a.z + a.w;
                const float u01 = bb.x + bb.y, u23 = bb.z + bb.w;
                const float v01 = cc.x + cc.y;
                cs0 += t01 + t23;   // cols 8c..8c+3
                cs1 += t23 + u01;   // cols 8c+2..8c+5
                cs2 += u01 + u23;   // cols 8c+4..8c+7
                cs3 += u23 + v01;   // cols 8c+6..8c+9

                // squares once per element, then shared pair sums
                const float sa01 = fmaf(a.x, a.x, a.y * a.y);
                const float sa23 = fmaf(a.z, a.z, a.w * a.w);
                const float sb01 = fmaf(bb.x, bb.x, bb.y * bb.y);
                const float sb23 = fmaf(bb.z, bb.z, bb.w * bb.w);
                const float sc01 = fmaf(cc.x, cc.x, cc.y * cc.y);
                cq0 += sa01 + sa23;
                cq1 += sa23 + sb01;
                cq2 += sb01 + sb23;
                cq3 += sb23 + sc01;
            }
        }

        if (j > 0) {
            const int orow = r0 + j - 1;
            if (orow < H_OUT) {
                float* orow_p = outb + (size_t)orow * W_OUT;
                const float s0 = ps0 + cs0, q0 = pq0 + cq0;
                const float s1 = ps1 + cs1, q1 = pq1 + cq1;
                const float s2 = ps2 + cs2, q2 = pq2 + cq2;
                const float s3 = ps3 + cs3, q3 = pq3 + cq3;

                const float m0 = s0 * inv_n, m1 = s1 * inv_n;
                const float m2 = s2 * inv_n, m3 = s3 * inv_n;
                const float r0v = sqrtf(fmaxf(fmaf(-m0, m0, q0 * inv_n), 0.f));
                const float r1v = sqrtf(fmaxf(fmaf(-m1, m1, q1 * inv_n), 0.f));
                const float r2v = sqrtf(fmaxf(fmaf(-m2, m2, q2 * inv_n), 0.f));
                const float r3v = sqrtf(fmaxf(fmaf(-m3, m3, q3 * inv_n), 0.f));

                // streaming stores: output has zero reuse, keep L2 for input
                __stcs(orow_p + oc0 + 0, r0v);
                __stcs(orow_p + oc0 + 1, r1v);
                __stcs(orow_p + oc0 + 2, r2v);
                if (oc0 + 3 < W_OUT) __stcs(orow_p + oc0 + 3, r3v);
            }
        }
        ps0 = cs0; ps1 = cs1; ps2 = cs2; ps3 = cs3;
        pq0 = cq0; pq1 = cq1; pq2 = cq2; pq3 = cq3;
    }
}

extern "C" void kernel_launch(void* const* d_in, const int* in_sizes, int n_in,
                              void* d_out, int out_size) {
    const float* in = (const float*)d_in[0];
    float* out = (float*)d_out;
    (void)in_sizes; (void)n_in; (void)out_size;

    // 128 col-quad threads cover 511 output cols; 64 strips of 8 rows; 64 batches.
    dim3 block(128, 2, 1);
    dim3 grid(1, 32, 64);
    std_pool_kernel<<<grid, block>>>(in, out);
}

// round 5
// speedup vs baseline: 1.0714x; 1.0714x over previous
#include <cuda_runtime.h>
#include <cuda_bf16.h>

// StandardDeviationPooling: 4x4 window, stride 2, VALID.
// Input:  [64, 1024, 1024, 1] fp32   Output: [64, 511*511] fp32
// std = sqrt(max(E[x^2] - E[x]^2, 0)) per window.
//
// R5: shuffle-deduped loads. Each thread loads exactly ONE float4 per input
// row (warp = 512B contiguous, zero overlap). Horizontal window overlap is
// resolved with __shfl_down_sync of row-pair partial sums; lane 31 patches
// the warp boundary with a predicated float2 load. 2 output cols x 8 output
// rows per thread, rolling 2-row pair sums (each input row loaded once).

#define H_IN 1024
#define W_IN 1024
#define H_OUT 511
#define W_OUT 511
#define ROWS_PER_THREAD 8

__global__ __launch_bounds__(256, 4)
void std_pool_kernel(const float* __restrict__ in, float* __restrict__ out) {
    const int c    = threadIdx.x;                 // col-pair index 0..255
    const int lane = c & 31;
    const int r0   = blockIdx.y * ROWS_PER_THREAD;
    const int b    = blockIdx.z;

    const float* __restrict__ inb  = in  + (size_t)b * H_IN * W_IN;
    float* __restrict__       outb = out + (size_t)b * H_OUT * W_OUT;

    const int  ic       = 4 * c;                  // own float4: cols 4c..4c+3
    const int  oc0      = 2 * c;
    const bool is_edge  = (lane == 31);
    const bool edge_ok  = is_edge && (ic + 5) < W_IN;   // lane-31 patch in bounds
    const float inv_n   = 1.0f / 16.0f;

    // previous row-pair sums/sumsq for the 2 output cols
    float ps0 = 0.f, ps1 = 0.f, pq0 = 0.f, pq1 = 0.f;

    #pragma unroll
    for (int j = 0; j <= ROWS_PER_THREAD; ++j) {
        const int irow = 2 * (r0 + j);

        // own row-pair partials: cols (4c,4c+1) and (4c+2,4c+3)
        float own01 = 0.f, own23 = 0.f, oq01 = 0.f, oq23 = 0.f;
        float e01 = 0.f, eq01 = 0.f;              // lane-31 boundary patch

        if (irow + 1 < H_IN) {
            #pragma unroll
            for (int rr = 0; rr < 2; ++rr) {
                const float* rowp = inb + (size_t)(irow + rr) * W_IN + ic;
                const float4 a = *reinterpret_cast<const float4*>(rowp);
                own01 += a.x + a.y;
                own23 += a.z + a.w;
                oq01 = fmaf(a.x, a.x, fmaf(a.y, a.y, oq01));
                oq23 = fmaf(a.z, a.z, fmaf(a.w, a.w, oq23));
                if (edge_ok) {
                    const float2 e = *reinterpret_cast<const float2*>(rowp + 4);
                    e01  += e.x + e.y;
                    eq01  = fmaf(e.x, e.x, fmaf(e.y, e.y, eq01));
                }
            }
        }

        // neighbor's (4c+4,4c+5) row-pair partials come from lane+1
        float n01  = __shfl_down_sync(0xffffffffu, own01, 1);
        float nq01 = __shfl_down_sync(0xffffffffu, oq01, 1);
        if (is_edge) { n01 = e01; nq01 = eq01; }

        const float cs0 = own01 + own23;
        const float cs1 = own23 + n01;
        const float cq0 = oq01 + oq23;
        const float cq1 = oq23 + nq01;

        if (j > 0) {
            const int orow = r0 + j - 1;
            if (orow < H_OUT) {
                float* orow_p = outb + (size_t)orow * W_OUT;
                {
                    const float s = ps0 + cs0, q = pq0 + cq0;
                    const float m = s * inv_n;
                    __stcs(orow_p + oc0, sqrtf(fmaxf(fmaf(-m, m, q * inv_n), 0.f)));
                }
                if (oc0 + 1 < W_OUT) {
                    const float s = ps1 + cs1, q = pq1 + cq1;
                    const float m = s * inv_n;
                    __stcs(orow_p + oc0 + 1, sqrtf(fmaxf(fmaf(-m, m, q * inv_n), 0.f)));
                }
            }
        }
        ps0 = cs0; ps1 = cs1; pq0 = cq0; pq1 = cq1;
    }
}

extern "C" void kernel_launch(void* const* d_in, const int* in_sizes, int n_in,
                              void* d_out, int out_size) {
    const float* in = (const float*)d_in[0];
    float* out = (float*)d_out;
    (void)in_sizes; (void)n_in; (void)out_size;

    // 256 col-pair threads cover 511 output cols; 64 strips of 8 rows; 64 batches.
    dim3 block(256, 1, 1);
    dim3 grid(1, (H_OUT + ROWS_PER_THREAD - 1) / ROWS_PER_THREAD, 64);
    std_pool_kernel<<<grid, block>>>(in, out);
}